// round 8
// baseline (speedup 1.0000x reference)
#include <cuda_runtime.h>
#include <math.h>

#define BB 8
#define PP 4096
#define CC 91
#define CM1 90
#define FD 1024
#define DETS 100
#define ROWCAP 512
#define CANDCAP 1024
#define BBOX_CLIP 4.135166556742356f
#define IMGF 800.0f
#define RT 32                       // rows per block in rowmax_k
#define STR 100                     // padded smem row stride (floats)

__device__ unsigned int g_rowmax[BB * PP];
__device__ int g_keptp[BB * DETS];

// ---------------------------------------------------------------------------
// K1: 8 threads per row, 32 rows/block, 256 threads, grid=1024 (6.9/SM,
// ~1.5% wave tail). Stage 32 rows = 728 float4 via 3 LDG.128/thread,
// scattered into smem padded to stride 100 (cols 91..95 = -1e30). Compute:
// 3 conflict-free LDS.128 per thread, 12 MUFU exp, 11 FMAX, 3-level shuffle.
// score = __expf(maxlogit_1_90) / sum(exp(all logits)); |logit|<~6 so no
// max-subtract needed for fp32 safety.
// ---------------------------------------------------------------------------
__global__ void __launch_bounds__(256) rowmax_k(const float* __restrict__ logits) {
    __shared__ float s[RT * STR];              // 12800 bytes
    int tid = threadIdx.x;
    const float4* src = (const float4*)(logits + (size_t)blockIdx.x * RT * CC); // 728 f4
    #pragma unroll
    for (int k = 0; k < 3; k++) {
        int i = tid + k * 256;
        if (i < 728) {
            float4 v = src[i];
            int e = 4 * i;
            int r0 = e / 91,      c0 = e - 91 * r0;
            int r1 = (e + 1) / 91, c1 = (e + 1) - 91 * r1;
            int r2 = (e + 2) / 91, c2 = (e + 2) - 91 * r2;
            int r3 = (e + 3) / 91, c3 = (e + 3) - 91 * r3;
            s[r0 * STR + c0] = v.x;
            s[r1 * STR + c1] = v.y;
            s[r2 * STR + c2] = v.z;
            s[r3 * STR + c3] = v.w;
        }
    }
    if (tid < 160) {                           // pad cols 91..95 of 32 rows
        int r = tid / 5, c = 91 + tid % 5;
        s[r * STR + c] = -1e30f;
    }
    __syncthreads();

    int row = tid >> 3, sub = tid & 7;
    const float4* r4 = (const float4*)(s + row * STR + sub * 12);
    float4 A = r4[0], B = r4[1], C = r4[2];

    float sum = ((__expf(A.x) + __expf(A.y)) + (__expf(A.z) + __expf(A.w)))
              + ((__expf(B.x) + __expf(B.y)) + (__expf(B.z) + __expf(B.w)))
              + ((__expf(C.x) + __expf(C.y)) + (__expf(C.z) + __expf(C.w)));

    float ax = (sub == 0) ? -1e30f : A.x;      // class 0 excluded from max
    float m = fmaxf(fmaxf(fmaxf(ax, A.y), fmaxf(A.z, A.w)),
                    fmaxf(fmaxf(fmaxf(B.x, B.y), fmaxf(B.z, B.w)),
                          fmaxf(fmaxf(C.x, C.y), fmaxf(C.z, C.w))));

    #pragma unroll
    for (int o = 1; o < 8; o <<= 1) {
        sum += __shfl_xor_sync(0xffffffffu, sum, o);
        m = fmaxf(m, __shfl_xor_sync(0xffffffffu, m, o));
    }

    if (sub == 0)
        g_rowmax[blockIdx.x * RT + row] = __float_as_uint(__expf(m) / sum);
}

// ---------------------------------------------------------------------------
// Warp-parallel descending threshold search over 256-bin histogram.
// ---------------------------------------------------------------------------
__device__ __forceinline__ void find_thresh(const int* h, int need, int* s_b, int* s_cum) {
    int L = threadIdx.x;              // tid < 32 only
    int hi = 255 - 8 * L;
    int hb[8], cs = 0;
    #pragma unroll
    for (int j = 0; j < 8; j++) { hb[j] = h[hi - j]; cs += hb[j]; }
    int pref = cs;
    #pragma unroll
    for (int o = 1; o < 32; o <<= 1) {
        int t = __shfl_up_sync(0xffffffffu, pref, o);
        if (L >= o) pref += t;
    }
    int above = pref - cs;
    if (above < need && need <= pref) {
        int cum = above;
        #pragma unroll
        for (int j = 0; j < 8; j++) {
            if (cum + hb[j] >= need) { *s_b = hi - j; *s_cum = cum; break; }
            cum += hb[j];
        }
    }
}

// ---------------------------------------------------------------------------
// K2: one block (512 threads) per image. 2-level radix threshold on approx
// rowmaxes (with margins), compact rows, exact re-softmax, exact top-100 by
// rank-counting on (score_bits<<32)|~idx keys, decode+clip+scale boxes.
// ---------------------------------------------------------------------------
__global__ void __launch_bounds__(512, 1) select_k(const float* __restrict__ logits,
                                                   const float* __restrict__ reg,
                                                   const float* __restrict__ props,
                                                   float* __restrict__ out) {
    __shared__ unsigned vals[PP];
    __shared__ int h[256];
    __shared__ int rowbuf[ROWCAP];
    __shared__ unsigned long long cand[CANDCAP];
    __shared__ int s_nrows, s_ncand, s_b1, s_cumAbove, s_fb, s_fcum;

    int img = blockIdx.x;
    int tid = threadIdx.x;
    int lane = tid & 31;

    for (int i = tid; i < PP; i += 512) vals[i] = g_rowmax[img * PP + i];
    if (tid < 256) h[tid] = 0;
    if (tid == 0) { s_nrows = 0; s_ncand = 0; }
    __syncthreads();
    for (int i = tid; i < PP; i += 512) {
        int bin = vals[i] >> 22;
        unsigned peers = __match_any_sync(0xffffffffu, bin);
        if (lane == __ffs(peers) - 1) atomicAdd(&h[bin], __popc(peers));
    }
    __syncthreads();
    if (tid < 32) find_thresh(h, DETS, &s_b1, &s_cumAbove);
    __syncthreads();
    int b1 = s_b1;

    if (tid < 256) h[tid] = 0;
    __syncthreads();
    for (int i = tid; i < PP; i += 512) {
        unsigned v = vals[i];
        bool pred = ((int)(v >> 22) == b1);
        unsigned active = __ballot_sync(0xffffffffu, pred);
        if (pred) {
            int bin = (v >> 14) & 0xFF;
            unsigned peers = __match_any_sync(active, bin);
            if (lane == __ffs(peers) - 1) atomicAdd(&h[bin], __popc(peers));
        }
    }
    __syncthreads();
    if (tid < 32) find_thresh(h, DETS - s_cumAbove, &s_fb, &s_fcum);
    __syncthreads();
    unsigned T = ((unsigned)b1 << 8) | (unsigned)s_fb;
    unsigned Tc = (T >= 2) ? T - 2 : 0;   // row compaction threshold (approx margin)
    unsigned Te = (T >= 1) ? T - 1 : 0;   // candidate emission threshold

    for (int i = tid; i < PP; i += 512) {
        bool keep = (vals[i] >> 14) >= Tc;
        unsigned b = __ballot_sync(0xffffffffu, keep);
        int cnt = __popc(b);
        if (cnt) {
            int basepos = 0;
            if (lane == 0) basepos = atomicAdd(&s_nrows, cnt);
            basepos = __shfl_sync(0xffffffffu, basepos, 0);
            if (keep) {
                int pos = basepos + __popc(b & ((1u << lane) - 1));
                if (pos < ROWCAP) rowbuf[pos] = i;
            }
        }
    }
    __syncthreads();
    int nrows = min(s_nrows, ROWCAP);

    int warp = tid >> 5;
    for (int r = warp; r < nrows; r += 16) {
        int p = rowbuf[r];
        const float* l = logits + (size_t)(img * PP + p) * CC;
        float v0 = l[lane];
        float v1 = l[lane + 32];
        float v2 = (lane < 27) ? l[lane + 64] : -1e30f;
        float m = fmaxf(v0, fmaxf(v1, v2));
        #pragma unroll
        for (int o = 16; o; o >>= 1) m = fmaxf(m, __shfl_xor_sync(0xffffffffu, m, o));
        float e0 = expf(v0 - m);
        float e1 = expf(v1 - m);
        float e2 = (lane < 27) ? expf(v2 - m) : 0.0f;
        float s = e0 + e1 + e2;
        #pragma unroll
        for (int o = 16; o; o >>= 1) s += __shfl_xor_sync(0xffffffffu, s, o);

        unsigned base = (unsigned)p * CM1;
        if (lane > 0) {
            unsigned b = __float_as_uint(e0 / s);
            if ((b >> 14) >= Te) {
                int pos = atomicAdd(&s_ncand, 1);
                if (pos < CANDCAP)
                    cand[pos] = (((unsigned long long)b) << 32) | (unsigned)(~(base + lane - 1));
            }
        }
        {
            unsigned b = __float_as_uint(e1 / s);
            if ((b >> 14) >= Te) {
                int pos = atomicAdd(&s_ncand, 1);
                if (pos < CANDCAP)
                    cand[pos] = (((unsigned long long)b) << 32) | (unsigned)(~(base + lane + 31));
            }
        }
        if (lane < 27) {
            unsigned b = __float_as_uint(e2 / s);
            if ((b >> 14) >= Te) {
                int pos = atomicAdd(&s_ncand, 1);
                if (pos < CANDCAP)
                    cand[pos] = (((unsigned long long)b) << 32) | (unsigned)(~(base + lane + 63));
            }
        }
    }
    __syncthreads();

    int nc = min(s_ncand, CANDCAP);
    for (int i = tid; i < nc; i += 512) {
        unsigned long long my = cand[i];
        int rank = 0;
        for (int j = 0; j < nc; j++) rank += (cand[j] > my);
        if (rank < DETS) {
            unsigned idxl = ~(unsigned)(my & 0xFFFFFFFFull);
            int p = idxl / CM1;
            int c = idxl - p * CM1 + 1;

            const float* pr = props + ((size_t)img * PP + p) * 4;
            float x1 = pr[0], y1 = pr[1], x2 = pr[2], y2 = pr[3];
            float w = x2 - x1, hh = y2 - y1;
            float cx = x1 + 0.5f * w, cy = y1 + 0.5f * hh;

            const float* rg = reg + ((size_t)img * PP + p) * (4 * CC) + 4 * c;
            float dx = rg[0] / 10.0f;
            float dy = rg[1] / 10.0f;
            float dw = fminf(rg[2] / 5.0f, BBOX_CLIP);
            float dh = fminf(rg[3] / 5.0f, BBOX_CLIP);

            float pcx = dx * w + cx, pcy = dy * hh + cy;
            float pw = expf(dw) * w, ph = expf(dh) * hh;

            float bx1 = fminf(fmaxf(pcx - 0.5f * pw, 0.0f), IMGF);
            float by1 = fminf(fmaxf(pcy - 0.5f * ph, 0.0f), IMGF);
            float bx2 = fminf(fmaxf(pcx + 0.5f * pw, 0.0f), IMGF);
            float by2 = fminf(fmaxf(pcy + 0.5f * ph, 0.0f), IMGF);

            float* ob = out + ((size_t)img * DETS + rank) * 4;
            ob[0] = bx1 / IMGF;
            ob[1] = by1 / IMGF;
            ob[2] = bx2 / IMGF;
            ob[3] = by2 / IMGF;
            g_keptp[img * DETS + rank] = p;
        }
    }
}

// ---------------------------------------------------------------------------
// K3: feature gather, one block per detection, float4 vectorized
// ---------------------------------------------------------------------------
__global__ void gather_k(const float* __restrict__ feats, float* __restrict__ out) {
    int img = blockIdx.x / DETS;
    int p = g_keptp[blockIdx.x];
    const float4* src = (const float4*)(feats + ((size_t)img * PP + p) * FD);
    float4* dst = (float4*)(out + BB * DETS * 4 + (size_t)blockIdx.x * FD);
    dst[threadIdx.x] = src[threadIdx.x];
}

extern "C" void kernel_launch(void* const* d_in, const int* in_sizes, int n_in,
                              void* d_out, int out_size) {
    const float* logits = (const float*)d_in[0];
    const float* reg    = (const float*)d_in[1];
    const float* props  = (const float*)d_in[2];
    const float* feats  = (const float*)d_in[3];
    float* out = (float*)d_out;

    rowmax_k<<<BB * PP / RT, 256>>>(logits);
    select_k<<<BB, 512>>>(logits, reg, props, out);
    gather_k<<<BB * DETS, 256>>>(feats, out);
}

// round 9
// speedup vs baseline: 1.1954x; 1.1954x over previous
#include <cuda_runtime.h>
#include <math.h>

#define BB 8
#define PP 4096
#define CC 91
#define CM1 90
#define FD 1024
#define DETS 100
#define ROWCAP 512
#define CANDCAP 1024
#define BBOX_CLIP 4.135166556742356f
#define IMGF 800.0f
#define RT 32                       // rows per block in rowmax_k
#define STR 100                     // padded smem row stride (floats)

__device__ unsigned int g_rowmax[BB * PP];
__device__ int g_keptp[BB * DETS];

// ---------------------------------------------------------------------------
// K1 (best measured variant, 6.88us): 8 threads/row, 32 rows/block, 256 thr,
// grid=1024. Stage 728 float4 -> smem padded to stride 100, compute with
// 3 conflict-free LDS.128 + 12 MUFU exp + fmax tree + 3-level shuffle.
// ---------------------------------------------------------------------------
__global__ void __launch_bounds__(256) rowmax_k(const float* __restrict__ logits) {
    __shared__ float s[RT * STR];              // 12800 bytes
    int tid = threadIdx.x;
    const float4* src = (const float4*)(logits + (size_t)blockIdx.x * RT * CC); // 728 f4
    #pragma unroll
    for (int k = 0; k < 3; k++) {
        int i = tid + k * 256;
        if (i < 728) {
            float4 v = src[i];
            int e = 4 * i;
            int r0 = e / 91,      c0 = e - 91 * r0;
            int r1 = (e + 1) / 91, c1 = (e + 1) - 91 * r1;
            int r2 = (e + 2) / 91, c2 = (e + 2) - 91 * r2;
            int r3 = (e + 3) / 91, c3 = (e + 3) - 91 * r3;
            s[r0 * STR + c0] = v.x;
            s[r1 * STR + c1] = v.y;
            s[r2 * STR + c2] = v.z;
            s[r3 * STR + c3] = v.w;
        }
    }
    if (tid < 160) {                           // pad cols 91..95 of 32 rows
        int r = tid / 5, c = 91 + tid % 5;
        s[r * STR + c] = -1e30f;
    }
    __syncthreads();

    int row = tid >> 3, sub = tid & 7;
    const float4* r4 = (const float4*)(s + row * STR + sub * 12);
    float4 A = r4[0], B = r4[1], C = r4[2];

    float sum = ((__expf(A.x) + __expf(A.y)) + (__expf(A.z) + __expf(A.w)))
              + ((__expf(B.x) + __expf(B.y)) + (__expf(B.z) + __expf(B.w)))
              + ((__expf(C.x) + __expf(C.y)) + (__expf(C.z) + __expf(C.w)));

    float ax = (sub == 0) ? -1e30f : A.x;      // class 0 excluded from max
    float m = fmaxf(fmaxf(fmaxf(ax, A.y), fmaxf(A.z, A.w)),
                    fmaxf(fmaxf(fmaxf(B.x, B.y), fmaxf(B.z, B.w)),
                          fmaxf(fmaxf(C.x, C.y), fmaxf(C.z, C.w))));

    #pragma unroll
    for (int o = 1; o < 8; o <<= 1) {
        sum += __shfl_xor_sync(0xffffffffu, sum, o);
        m = fmaxf(m, __shfl_xor_sync(0xffffffffu, m, o));
    }

    if (sub == 0)
        g_rowmax[blockIdx.x * RT + row] = __float_as_uint(__expf(m) / sum);
}

// ---------------------------------------------------------------------------
// Warp-parallel descending threshold search over 256-bin histogram.
// Call with the first warp only (tid < 32).
// ---------------------------------------------------------------------------
__device__ __forceinline__ void find_thresh(const int* h, int need, int* s_b, int* s_cum) {
    int L = threadIdx.x;
    int hi = 255 - 8 * L;
    int hb[8], cs = 0;
    #pragma unroll
    for (int j = 0; j < 8; j++) { hb[j] = h[hi - j]; cs += hb[j]; }
    int pref = cs;
    #pragma unroll
    for (int o = 1; o < 32; o <<= 1) {
        int t = __shfl_up_sync(0xffffffffu, pref, o);
        if (L >= o) pref += t;
    }
    int above = pref - cs;
    if (above < need && need <= pref) {
        int cum = above;
        #pragma unroll
        for (int j = 0; j < 8; j++) {
            if (cum + hb[j] >= need) { *s_b = hi - j; *s_cum = cum; break; }
            cum += hb[j];
        }
    }
}

// ---------------------------------------------------------------------------
// K2: one block (1024 threads) per image. 2-level radix threshold on approx
// rowmaxes (with margins for __expf error), compact rows, exact re-softmax,
// exact top-100 by rank-counting, decode + clip + scale boxes.
// ---------------------------------------------------------------------------
__global__ void __launch_bounds__(1024, 1) select_k(const float* __restrict__ logits,
                                                    const float* __restrict__ reg,
                                                    const float* __restrict__ props,
                                                    float* __restrict__ out) {
    __shared__ unsigned vals[PP];
    __shared__ int h[256];
    __shared__ int rowbuf[ROWCAP];
    __shared__ unsigned long long cand[CANDCAP];
    __shared__ int s_nrows, s_ncand, s_b1, s_cumAbove, s_fb, s_fcum;

    int img = blockIdx.x;
    int tid = threadIdx.x;
    int lane = tid & 31;

    for (int i = tid; i < PP; i += 1024) vals[i] = g_rowmax[img * PP + i];
    if (tid < 256) h[tid] = 0;
    if (tid == 0) { s_nrows = 0; s_ncand = 0; }
    __syncthreads();
    for (int i = tid; i < PP; i += 1024) {
        int bin = vals[i] >> 22;
        unsigned peers = __match_any_sync(0xffffffffu, bin);
        if (lane == __ffs(peers) - 1) atomicAdd(&h[bin], __popc(peers));
    }
    __syncthreads();
    if (tid < 32) find_thresh(h, DETS, &s_b1, &s_cumAbove);
    __syncthreads();
    int b1 = s_b1;

    if (tid < 256) h[tid] = 0;
    __syncthreads();
    for (int i = tid; i < PP; i += 1024) {
        unsigned v = vals[i];
        bool pred = ((int)(v >> 22) == b1);
        unsigned active = __ballot_sync(0xffffffffu, pred);
        if (pred) {
            int bin = (v >> 14) & 0xFF;
            unsigned peers = __match_any_sync(active, bin);
            if (lane == __ffs(peers) - 1) atomicAdd(&h[bin], __popc(peers));
        }
    }
    __syncthreads();
    if (tid < 32) find_thresh(h, DETS - s_cumAbove, &s_fb, &s_fcum);
    __syncthreads();
    unsigned T = ((unsigned)b1 << 8) | (unsigned)s_fb;
    unsigned Tc = (T >= 2) ? T - 2 : 0;   // row compaction threshold (approx margin)
    unsigned Te = (T >= 1) ? T - 1 : 0;   // candidate emission threshold

    for (int i = tid; i < PP; i += 1024) {
        bool keep = (vals[i] >> 14) >= Tc;
        unsigned b = __ballot_sync(0xffffffffu, keep);
        int cnt = __popc(b);
        if (cnt) {
            int basepos = 0;
            if (lane == 0) basepos = atomicAdd(&s_nrows, cnt);
            basepos = __shfl_sync(0xffffffffu, basepos, 0);
            if (keep) {
                int pos = basepos + __popc(b & ((1u << lane) - 1));
                if (pos < ROWCAP) rowbuf[pos] = i;
            }
        }
    }
    __syncthreads();
    int nrows = min(s_nrows, ROWCAP);

    int warp = tid >> 5;
    for (int r = warp; r < nrows; r += 32) {
        int p = rowbuf[r];
        const float* l = logits + (size_t)(img * PP + p) * CC;
        float v0 = l[lane];
        float v1 = l[lane + 32];
        float v2 = (lane < 27) ? l[lane + 64] : -1e30f;
        float m = fmaxf(v0, fmaxf(v1, v2));
        #pragma unroll
        for (int o = 16; o; o >>= 1) m = fmaxf(m, __shfl_xor_sync(0xffffffffu, m, o));
        float e0 = expf(v0 - m);
        float e1 = expf(v1 - m);
        float e2 = (lane < 27) ? expf(v2 - m) : 0.0f;
        float s = e0 + e1 + e2;
        #pragma unroll
        for (int o = 16; o; o >>= 1) s += __shfl_xor_sync(0xffffffffu, s, o);

        unsigned base = (unsigned)p * CM1;
        if (lane > 0) {
            unsigned b = __float_as_uint(e0 / s);
            if ((b >> 14) >= Te) {
                int pos = atomicAdd(&s_ncand, 1);
                if (pos < CANDCAP)
                    cand[pos] = (((unsigned long long)b) << 32) | (unsigned)(~(base + lane - 1));
            }
        }
        {
            unsigned b = __float_as_uint(e1 / s);
            if ((b >> 14) >= Te) {
                int pos = atomicAdd(&s_ncand, 1);
                if (pos < CANDCAP)
                    cand[pos] = (((unsigned long long)b) << 32) | (unsigned)(~(base + lane + 31));
            }
        }
        if (lane < 27) {
            unsigned b = __float_as_uint(e2 / s);
            if ((b >> 14) >= Te) {
                int pos = atomicAdd(&s_ncand, 1);
                if (pos < CANDCAP)
                    cand[pos] = (((unsigned long long)b) << 32) | (unsigned)(~(base + lane + 63));
            }
        }
    }
    __syncthreads();

    int nc = min(s_ncand, CANDCAP);
    for (int i = tid; i < nc; i += 1024) {
        unsigned long long my = cand[i];
        int rank = 0;
        for (int j = 0; j < nc; j++) rank += (cand[j] > my);
        if (rank < DETS) {
            unsigned idxl = ~(unsigned)(my & 0xFFFFFFFFull);
            int p = idxl / CM1;
            int c = idxl - p * CM1 + 1;

            const float* pr = props + ((size_t)img * PP + p) * 4;
            float x1 = pr[0], y1 = pr[1], x2 = pr[2], y2 = pr[3];
            float w = x2 - x1, hh = y2 - y1;
            float cx = x1 + 0.5f * w, cy = y1 + 0.5f * hh;

            const float* rg = reg + ((size_t)img * PP + p) * (4 * CC) + 4 * c;
            float dx = rg[0] / 10.0f;
            float dy = rg[1] / 10.0f;
            float dw = fminf(rg[2] / 5.0f, BBOX_CLIP);
            float dh = fminf(rg[3] / 5.0f, BBOX_CLIP);

            float pcx = dx * w + cx, pcy = dy * hh + cy;
            float pw = expf(dw) * w, ph = expf(dh) * hh;

            float bx1 = fminf(fmaxf(pcx - 0.5f * pw, 0.0f), IMGF);
            float by1 = fminf(fmaxf(pcy - 0.5f * ph, 0.0f), IMGF);
            float bx2 = fminf(fmaxf(pcx + 0.5f * pw, 0.0f), IMGF);
            float by2 = fminf(fmaxf(pcy + 0.5f * ph, 0.0f), IMGF);

            float* ob = out + ((size_t)img * DETS + rank) * 4;
            ob[0] = bx1 / IMGF;
            ob[1] = by1 / IMGF;
            ob[2] = bx2 / IMGF;
            ob[3] = by2 / IMGF;
            g_keptp[img * DETS + rank] = p;
        }
    }
}

// ---------------------------------------------------------------------------
// K3: feature gather, one block per detection, float4 vectorized
// ---------------------------------------------------------------------------
__global__ void gather_k(const float* __restrict__ feats, float* __restrict__ out) {
    int img = blockIdx.x / DETS;
    int p = g_keptp[blockIdx.x];
    const float4* src = (const float4*)(feats + ((size_t)img * PP + p) * FD);
    float4* dst = (float4*)(out + BB * DETS * 4 + (size_t)blockIdx.x * FD);
    dst[threadIdx.x] = src[threadIdx.x];
}

extern "C" void kernel_launch(void* const* d_in, const int* in_sizes, int n_in,
                              void* d_out, int out_size) {
    const float* logits = (const float*)d_in[0];
    const float* reg    = (const float*)d_in[1];
    const float* props  = (const float*)d_in[2];
    const float* feats  = (const float*)d_in[3];
    float* out = (float*)d_out;

    rowmax_k<<<BB * PP / RT, 256>>>(logits);
    select_k<<<BB, 1024>>>(logits, reg, props, out);
    gather_k<<<BB * DETS, 256>>>(feats, out);
}